// round 8
// baseline (speedup 1.0000x reference)
#include <cuda_runtime.h>
#include <cstdint>

#define Bz    4
#define Cc    64
#define Hh    64
#define Ww    64
#define HW    4096
#define CHW   (Cc*HW)
#define PATCH 9
#define CHUNK 16
#define NCH   (Cc/CHUNK)            // 4
#define TY    2                     // rows per CTA
#define XW    32                    // x extent per CTA
#define SROW  40                    // 4 | 32 | 4
#define SROWS (TY+8)                // 10
#define F2BUF (CHUNK*SROWS*SROW)    // 6400 floats
#define F1BUF (CHUNK*TY*XW)         // 1024 floats
#define SMEM_FLOATS (2*(F2BUF+F1BUF))  // 14848
#define SMEM_BYTES  (SMEM_FLOATS*4)    // 59392
#define NTHR  288                   // 9 warps (warp = dy)
#define NARRIVE (CHUNK*SROWS + CHUNK*TY)  // 192

typedef unsigned long long u64;

// scratch
__device__ float g_inv1[Bz][HW];
__device__ float g_inv2p[Bz][72][72];   // padded inverse norms of f2 (halo = 1.0)

__device__ __forceinline__ uint32_t smem_u32(const void* p) {
    uint32_t a;
    asm("{ .reg .u64 t; cvta.to.shared.u64 t, %1; cvt.u32.u64 %0, t; }" : "=r"(a) : "l"(p));
    return a;
}
__device__ __forceinline__ void bulk_g2s(uint32_t dst, const float* src, uint32_t bytes,
                                         uint32_t mbar) {
    asm volatile("cp.async.bulk.shared::cta.global.mbarrier::complete_tx::bytes "
                 "[%0], [%1], %2, [%3];"
                 :: "r"(dst), "l"(src), "r"(bytes), "r"(mbar) : "memory");
}
__device__ __forceinline__ void mbar_init(uint32_t mbar, uint32_t cnt) {
    asm volatile("mbarrier.init.shared.b64 [%0], %1;" :: "r"(mbar), "r"(cnt) : "memory");
}
__device__ __forceinline__ void mbar_arrive_tx(uint32_t mbar, uint32_t tx) {
    asm volatile("mbarrier.arrive.expect_tx.shared.b64 _, [%0], %1;"
                 :: "r"(mbar), "r"(tx) : "memory");
}
__device__ __forceinline__ void mbar_arrive(uint32_t mbar) {
    asm volatile("mbarrier.arrive.shared.b64 _, [%0];" :: "r"(mbar) : "memory");
}
__device__ __forceinline__ void mbar_wait(uint32_t mbar, uint32_t parity) {
    uint32_t done;
    asm volatile("{\n\t.reg .pred p;\n\t"
                 "mbarrier.try_wait.parity.acquire.cta.shared::cta.b64 p, [%1], %2;\n\t"
                 "selp.b32 %0, 1, 0, p;\n\t}"
                 : "=r"(done) : "r"(mbar), "r"(parity) : "memory");
    if (!done) {
        asm volatile("{\n\t.reg .pred P1;\n\t"
                     "WL_%=:\n\t"
                     "mbarrier.try_wait.parity.acquire.cta.shared::cta.b64 P1, [%0], %1, 0x989680;\n\t"
                     "@P1 bra.uni WD_%=;\n\t"
                     "bra.uni WL_%=;\n\t"
                     "WD_%=:\n\t}"
                     :: "r"(mbar), "r"(parity) : "memory");
    }
}
__device__ __forceinline__ u64 pk(float lo, float hi) {
    u64 r; asm("mov.b64 %0, {%1, %2};" : "=l"(r) : "f"(lo), "f"(hi)); return r;
}
__device__ __forceinline__ void fma2(u64& d, u64 a, u64 b) {
    asm("fma.rn.f32x2 %0, %1, %2, %0;" : "+l"(d) : "l"(a), "l"(b));
}
__device__ __forceinline__ void unpk(u64 p, float& lo, float& hi) {
    asm("mov.b64 {%0, %1}, %2;" : "=f"(lo), "=f"(hi) : "l"(p));
}

// ---------------------------------------------------------------------------
// Kernel 1: inverse L2 norms. 32768 threads, MLP=16, shfl-reduce. (proven)
// ---------------------------------------------------------------------------
__global__ void invnorm_kernel(const float* __restrict__ f1,
                               const float* __restrict__ f2) {
    int idx  = blockIdx.x * 256 + threadIdx.x;
    int cg   = idx & 3;
    int quad = (idx >> 2) & 1023;
    int b    = (idx >> 12) & 3;
    int feat = idx >> 14;
    const float* src = (feat ? f2 : f1) + b * CHW + quad * 4 + cg * 16 * HW;

    float4 s = make_float4(0.f, 0.f, 0.f, 0.f);
#pragma unroll
    for (int i = 0; i < 16; ++i) {
        float4 v = __ldg((const float4*)(src + i * HW));
        s.x += v.x * v.x; s.y += v.y * v.y; s.z += v.z * v.z; s.w += v.w * v.w;
    }
#pragma unroll
    for (int m = 1; m <= 2; m <<= 1) {
        s.x += __shfl_xor_sync(0xffffffffu, s.x, m);
        s.y += __shfl_xor_sync(0xffffffffu, s.y, m);
        s.z += __shfl_xor_sync(0xffffffffu, s.z, m);
        s.w += __shfl_xor_sync(0xffffffffu, s.w, m);
    }
    if (cg == 0) {
        float4 r;
        r.x = rsqrtf(s.x + 1e-6f); r.y = rsqrtf(s.y + 1e-6f);
        r.z = rsqrtf(s.z + 1e-6f); r.w = rsqrtf(s.w + 1e-6f);
        int y = quad >> 4, x = (quad & 15) << 2;
        if (feat == 0) *(float4*)&g_inv1[b][quad * 4] = r;
        else           *(float4*)&g_inv2p[b][y + 4][x + 4] = r;
    }
    if (idx < Bz * 72 * 72) {
        int bb = idx / 5184;
        int rc = idx - bb * 5184;
        int r  = rc / 72, cc = rc - r * 72;
        if (r < 4 || r >= 68 || cc < 4 || cc >= 68)
            g_inv2p[bb][r][cc] = 1.0f;
    }
}

// ---------------------------------------------------------------------------
// Kernel 2: correlation + relu.
//   grid = [b:4][ypair:32][xhalf:2] = 256 CTAs, 288 threads (9 warps).
//   warp = dy; lane = (ch:1)(ty:1)(xq:3) -> 4 px of row y0+ty, half the chans.
//   Channel halves combined in-warp via float shfl_xor(16).
// ---------------------------------------------------------------------------
__global__ __launch_bounds__(NTHR, 2)
void corr_kernel(const float* __restrict__ f1,
                 const float* __restrict__ f2,
                 float* __restrict__ out) {
    extern __shared__ float smem[];
    __shared__ u64 s_mbar[2];

    float* s_f2 = smem;
    float* s_f1 = smem + 2 * F2BUF;
    const uint32_t s2 = smem_u32(s_f2);
    const uint32_t s1 = smem_u32(s_f1);
    const uint32_t mb0 = smem_u32(&s_mbar[0]);
    const uint32_t mb1 = smem_u32(&s_mbar[1]);

    const int b    = blockIdx.x >> 6;
    const int y0   = ((blockIdx.x >> 1) & 31) * TY;
    const int h    = blockIdx.x & 1;             // x half
    const int xb   = h * XW;                     // global x base
    const int tid  = threadIdx.x;
    const int dy   = tid >> 5;                   // warp = dy (0..8)
    const int lane = tid & 31;
    const int ch   = lane >> 4;                  // channel parity
    const int ty   = (lane >> 3) & 1;            // row in pair
    const int xq   = lane & 7;                   // x quad (0..7)
    const int x0l  = xq << 2;                    // local x (0..28)
    const int y    = y0 + ty;
    const int xg   = xb + x0l;                   // global x

    const float* f2b = f2 + b * CHW;
    const float* f1b = f1 + b * CHW;

    const int scol = h ? (xb - 4) : 0;           // global start col of f2 copy
    const int dcol = h ? 0 : 4;                  // smem start col of f2 copy

    if (tid == 0) { mbar_init(mb0, NARRIVE); mbar_init(mb1, NARRIVE); }

    // one-time zeros: x-halo side + interiors of OOB rows, both buffers
    for (int i = tid; i < 2 * CHUNK * SROWS; i += NTHR) {
        int buf = i >= CHUNK * SROWS;
        int cr  = i - buf * CHUNK * SROWS;
        int c   = cr / SROWS, r = cr - c * SROWS;
        float* rowp = &s_f2[buf * F2BUF + (c * SROWS + r) * SROW];
        *(float4*)&rowp[h ? 36 : 0] = make_float4(0.f, 0.f, 0.f, 0.f);
        int row = y0 + r - 4;
        if (row < 0 || row >= Hh) {
            float4 z = make_float4(0.f, 0.f, 0.f, 0.f);
#pragma unroll
            for (int q = 0; q < 9; ++q) *(float4*)&rowp[dcol + q * 4] = z;
        }
    }
    __syncthreads();

    auto stage = [&](int c0, int sel) {
        uint32_t mb = sel ? mb1 : mb0;
        if (tid < CHUNK * SROWS) {                   // 160 f2-row copiers, 144B
            int c = tid / SROWS, r = tid - c * SROWS;
            int row = y0 + r - 4;
            if (row >= 0 && row < Hh) {
                mbar_arrive_tx(mb, 144);
                bulk_g2s(s2 + (uint32_t)((sel * F2BUF + (c * SROWS + r) * SROW + dcol) * 4),
                         f2b + (c0 + c) * HW + row * Ww + scol, 144, mb);
            } else {
                mbar_arrive(mb);
            }
        } else if (tid < NARRIVE) {                  // 32 f1 copiers, 128B
            int i = tid - CHUNK * SROWS;
            int c = i >> 1, r = i & 1;
            mbar_arrive_tx(mb, XW * 4);
            bulk_g2s(s1 + (uint32_t)((sel * F1BUF + c * (TY * XW) + r * XW) * 4),
                     f1b + (c0 + c) * HW + (y0 + r) * Ww + xb, XW * 4, mb);
        }
    };

    u64 acc2[PATCH][2];
#pragma unroll
    for (int i = 0; i < PATCH; ++i) { acc2[i][0] = 0ull; acc2[i][1] = 0ull; }

    stage(0, 0);
    stage(CHUNK, 1);

#pragma unroll 1
    for (int k = 0; k < NCH; ++k) {
        mbar_wait(k & 1 ? mb1 : mb0, (k >> 1) & 1);

        const float* sbuf = s_f2 + (k & 1) * F2BUF + (dy + ty) * SROW + x0l;
        const float* abuf = s_f1 + (k & 1) * F1BUF + ty * XW + x0l;
#pragma unroll
        for (int i = 0; i < CHUNK / 2; ++i) {
            const int c = (i << 1) + ch;
            ulonglong2 a2 = *(const ulonglong2*)(abuf + c * (TY * XW));
            const float* s = sbuf + c * (SROWS * SROW);
            float v[12];
            *(float4*)&v[0] = *(const float4*)(s);
            *(float4*)&v[4] = *(const float4*)(s + 4);
            *(float4*)&v[8] = *(const float4*)(s + 8);
            u64 p[11];
#pragma unroll
            for (int j = 0; j < 11; ++j) p[j] = pk(v[j], v[j + 1]);
#pragma unroll
            for (int d = 0; d < PATCH; ++d) {
                fma2(acc2[d][0], a2.x, p[d]);
                fma2(acc2[d][1], a2.y, p[d + 2]);
            }
        }
        if (k + 2 < NCH) {
            __syncthreads();
            stage((k + 2) * CHUNK, k & 1);
        }
    }

    // ---- combine channel halves in-warp (float adds; partner lane = xor 16)
    float a[PATCH][4];
#pragma unroll
    for (int d = 0; d < PATCH; ++d) {
        unpk(acc2[d][0], a[d][0], a[d][1]);
        unpk(acc2[d][1], a[d][2], a[d][3]);
#pragma unroll
        for (int j = 0; j < 4; ++j)
            a[d][j] += __shfl_xor_sync(0xffffffffu, a[d][j], 16);
    }

    if (ch == 0) {
        float4 iv1 = *(const float4*)(&g_inv1[b][y * Ww + xg]);
        float e[12];
        *(float4*)&e[0] = *(const float4*)(&g_inv2p[b][y + dy][xg]);
        *(float4*)&e[4] = *(const float4*)(&g_inv2p[b][y + dy][xg + 4]);
        *(float4*)&e[8] = *(const float4*)(&g_inv2p[b][y + dy][xg + 8]);

        float* op = out + (size_t)(b * 81 + dy * PATCH) * HW + y * Ww + xg;
#pragma unroll
        for (int d = 0; d < PATCH; ++d) {
            float4 o;
            o.x = fmaxf(a[d][0] * iv1.x * e[d + 0], 0.f);
            o.y = fmaxf(a[d][1] * iv1.y * e[d + 1], 0.f);
            o.z = fmaxf(a[d][2] * iv1.z * e[d + 2], 0.f);
            o.w = fmaxf(a[d][3] * iv1.w * e[d + 3], 0.f);
            *(float4*)(op + d * HW) = o;
        }
    }
}

// ---------------------------------------------------------------------------
extern "C" void kernel_launch(void* const* d_in, const int* in_sizes, int n_in,
                              void* d_out, int out_size) {
    const float* f1 = (const float*)d_in[0];
    const float* f2 = (const float*)d_in[1];
    float* out = (float*)d_out;

    cudaFuncSetAttribute(corr_kernel,
                         cudaFuncAttributeMaxDynamicSharedMemorySize, SMEM_BYTES);

    invnorm_kernel<<<128, 256>>>(f1, f2);
    corr_kernel<<<Bz * (Hh / TY) * 2, NTHR, SMEM_BYTES>>>(f1, f2, out);
}

// round 9
// speedup vs baseline: 1.1045x; 1.1045x over previous
#include <cuda_runtime.h>
#include <cstdint>

#define Bz    4
#define Cc    64
#define Hh    64
#define Ww    64
#define HW    4096
#define CHW   (Cc*HW)
#define PATCH 9
#define CHUNK 16
#define NCH   (Cc/CHUNK)            // 4
#define TY    2                     // rows per CTA
#define XW    32                    // x extent per CTA
#define SROW  40                    // 4 | 32 | 4
#define SROWS (TY+8)                // 10
#define F2BUF (CHUNK*SROWS*SROW)    // 6400 floats
#define F1BUF (CHUNK*TY*XW)         // 1024 floats
#define SMEM_FLOATS (2*(F2BUF+F1BUF))  // 14848
#define SMEM_BYTES  (SMEM_FLOATS*4)    // 59392
#define NTHR  288                   // 9 warps (warp = dy)
#define NARRIVE (CHUNK*SROWS + CHUNK*TY)  // 192

typedef unsigned long long u64;
union f2u { float2 f; u64 u; };

// scratch
__device__ float g_inv1[Bz][HW];
__device__ float g_inv2p[Bz][72][72];   // padded inverse norms of f2 (halo = 1.0)

__device__ __forceinline__ uint32_t smem_u32(const void* p) {
    uint32_t a;
    asm("{ .reg .u64 t; cvta.to.shared.u64 t, %1; cvt.u32.u64 %0, t; }" : "=r"(a) : "l"(p));
    return a;
}
__device__ __forceinline__ void bulk_g2s(uint32_t dst, const float* src, uint32_t bytes,
                                         uint32_t mbar) {
    asm volatile("cp.async.bulk.shared::cta.global.mbarrier::complete_tx::bytes "
                 "[%0], [%1], %2, [%3];"
                 :: "r"(dst), "l"(src), "r"(bytes), "r"(mbar) : "memory");
}
__device__ __forceinline__ void mbar_init(uint32_t mbar, uint32_t cnt) {
    asm volatile("mbarrier.init.shared.b64 [%0], %1;" :: "r"(mbar), "r"(cnt) : "memory");
}
__device__ __forceinline__ void mbar_arrive_tx(uint32_t mbar, uint32_t tx) {
    asm volatile("mbarrier.arrive.expect_tx.shared.b64 _, [%0], %1;"
                 :: "r"(mbar), "r"(tx) : "memory");
}
__device__ __forceinline__ void mbar_arrive(uint32_t mbar) {
    asm volatile("mbarrier.arrive.shared.b64 _, [%0];" :: "r"(mbar) : "memory");
}
__device__ __forceinline__ void mbar_wait(uint32_t mbar, uint32_t parity) {
    uint32_t done;
    asm volatile("{\n\t.reg .pred p;\n\t"
                 "mbarrier.try_wait.parity.acquire.cta.shared::cta.b64 p, [%1], %2;\n\t"
                 "selp.b32 %0, 1, 0, p;\n\t}"
                 : "=r"(done) : "r"(mbar), "r"(parity) : "memory");
    if (!done) {
        asm volatile("{\n\t.reg .pred P1;\n\t"
                     "WL_%=:\n\t"
                     "mbarrier.try_wait.parity.acquire.cta.shared::cta.b64 P1, [%0], %1, 0x989680;\n\t"
                     "@P1 bra.uni WD_%=;\n\t"
                     "bra.uni WL_%=;\n\t"
                     "WD_%=:\n\t}"
                     :: "r"(mbar), "r"(parity) : "memory");
    }
}
__device__ __forceinline__ u64 pk(float lo, float hi) {
    u64 r; asm("mov.b64 %0, {%1, %2};" : "=l"(r) : "f"(lo), "f"(hi)); return r;
}
__device__ __forceinline__ void fma2(u64& d, u64 a, u64 b) {
    asm("fma.rn.f32x2 %0, %1, %2, %0;" : "+l"(d) : "l"(a), "l"(b));
}
__device__ __forceinline__ void unpk(u64 p, float& lo, float& hi) {
    asm("mov.b64 {%0, %1}, %2;" : "=f"(lo), "=f"(hi) : "l"(p));
}

// ---------------------------------------------------------------------------
// Kernel 1: inverse L2 norms. 32768 threads, MLP=16, shfl-reduce. (proven)
// ---------------------------------------------------------------------------
__global__ void invnorm_kernel(const float* __restrict__ f1,
                               const float* __restrict__ f2) {
    int idx  = blockIdx.x * 256 + threadIdx.x;
    int cg   = idx & 3;
    int quad = (idx >> 2) & 1023;
    int b    = (idx >> 12) & 3;
    int feat = idx >> 14;
    const float* src = (feat ? f2 : f1) + b * CHW + quad * 4 + cg * 16 * HW;

    float4 s = make_float4(0.f, 0.f, 0.f, 0.f);
#pragma unroll
    for (int i = 0; i < 16; ++i) {
        float4 v = __ldg((const float4*)(src + i * HW));
        s.x += v.x * v.x; s.y += v.y * v.y; s.z += v.z * v.z; s.w += v.w * v.w;
    }
#pragma unroll
    for (int m = 1; m <= 2; m <<= 1) {
        s.x += __shfl_xor_sync(0xffffffffu, s.x, m);
        s.y += __shfl_xor_sync(0xffffffffu, s.y, m);
        s.z += __shfl_xor_sync(0xffffffffu, s.z, m);
        s.w += __shfl_xor_sync(0xffffffffu, s.w, m);
    }
    if (cg == 0) {
        float4 r;
        r.x = rsqrtf(s.x + 1e-6f); r.y = rsqrtf(s.y + 1e-6f);
        r.z = rsqrtf(s.z + 1e-6f); r.w = rsqrtf(s.w + 1e-6f);
        int y = quad >> 4, x = (quad & 15) << 2;
        if (feat == 0) *(float4*)&g_inv1[b][quad * 4] = r;
        else           *(float4*)&g_inv2p[b][y + 4][x + 4] = r;
    }
    if (idx < Bz * 72 * 72) {
        int bb = idx / 5184;
        int rc = idx - bb * 5184;
        int r  = rc / 72, cc = rc - r * 72;
        if (r < 4 || r >= 68 || cc < 4 || cc >= 68)
            g_inv2p[bb][r][cc] = 1.0f;
    }
}

// ---------------------------------------------------------------------------
// Kernel 2: correlation + relu.
//   grid = [b:4][ypair:32][xhalf:2] = 256 CTAs, 288 threads (9 warps).
//   warp = dy; lane = (ch:1)(ty:1)(xq:3) -> 4 px, half the channels.
//   Inner loop: aligned float2 pairs only; even dx via (px0,px1)/(px2,px3)
//   FFMA2, odd dx via (px1,px2) FFMA2 + 2 scalar FFMA. One pack per channel.
// ---------------------------------------------------------------------------
__global__ __launch_bounds__(NTHR, 2)
void corr_kernel(const float* __restrict__ f1,
                 const float* __restrict__ f2,
                 float* __restrict__ out) {
    extern __shared__ float smem[];
    __shared__ u64 s_mbar[2];

    float* s_f2 = smem;
    float* s_f1 = smem + 2 * F2BUF;
    const uint32_t s2 = smem_u32(s_f2);
    const uint32_t s1 = smem_u32(s_f1);
    const uint32_t mb0 = smem_u32(&s_mbar[0]);
    const uint32_t mb1 = smem_u32(&s_mbar[1]);

    const int b    = blockIdx.x >> 6;
    const int y0   = ((blockIdx.x >> 1) & 31) * TY;
    const int h    = blockIdx.x & 1;             // x half
    const int xb   = h * XW;                     // global x base
    const int tid  = threadIdx.x;
    const int dy   = tid >> 5;                   // warp = dy (0..8)
    const int lane = tid & 31;
    const int ch   = lane >> 4;                  // channel parity
    const int ty   = (lane >> 3) & 1;            // row in pair
    const int xq   = lane & 7;                   // x quad (0..7)
    const int x0l  = xq << 2;                    // local x (0..28)
    const int y    = y0 + ty;
    const int xg   = xb + x0l;                   // global x

    const float* f2b = f2 + b * CHW;
    const float* f1b = f1 + b * CHW;

    const int scol = h ? (xb - 4) : 0;           // global start col of f2 copy
    const int dcol = h ? 0 : 4;                  // smem start col of f2 copy

    if (tid == 0) { mbar_init(mb0, NARRIVE); mbar_init(mb1, NARRIVE); }

    // one-time zeros: x-halo side + interiors of OOB rows, both buffers
    for (int i = tid; i < 2 * CHUNK * SROWS; i += NTHR) {
        int buf = i >= CHUNK * SROWS;
        int cr  = i - buf * CHUNK * SROWS;
        int c   = cr / SROWS, r = cr - c * SROWS;
        float* rowp = &s_f2[buf * F2BUF + (c * SROWS + r) * SROW];
        *(float4*)&rowp[h ? 36 : 0] = make_float4(0.f, 0.f, 0.f, 0.f);
        int row = y0 + r - 4;
        if (row < 0 || row >= Hh) {
            float4 z = make_float4(0.f, 0.f, 0.f, 0.f);
#pragma unroll
            for (int q = 0; q < 9; ++q) *(float4*)&rowp[dcol + q * 4] = z;
        }
    }
    __syncthreads();

    auto stage = [&](int c0, int sel) {
        uint32_t mb = sel ? mb1 : mb0;
        if (tid < CHUNK * SROWS) {                   // 160 f2-row copiers, 144B
            int c = tid / SROWS, r = tid - c * SROWS;
            int row = y0 + r - 4;
            if (row >= 0 && row < Hh) {
                mbar_arrive_tx(mb, 144);
                bulk_g2s(s2 + (uint32_t)((sel * F2BUF + (c * SROWS + r) * SROW + dcol) * 4),
                         f2b + (c0 + c) * HW + row * Ww + scol, 144, mb);
            } else {
                mbar_arrive(mb);
            }
        } else if (tid < NARRIVE) {                  // 32 f1 copiers, 128B
            int i = tid - CHUNK * SROWS;
            int c = i >> 1, r = i & 1;
            mbar_arrive_tx(mb, XW * 4);
            bulk_g2s(s1 + (uint32_t)((sel * F1BUF + c * (TY * XW) + r * XW) * 4),
                     f1b + (c0 + c) * HW + (y0 + r) * Ww + xb, XW * 4, mb);
        }
    };

    // accumulators: even dx as (px0,px1)/(px2,px3) pairs; odd dx as (px1,px2)
    // pair + px0/px3 scalars.
    u64 eacc[5][2];
    u64 macc[4];
    float s0a[4], s3a[4];
#pragma unroll
    for (int e = 0; e < 5; ++e) { eacc[e][0] = 0ull; eacc[e][1] = 0ull; }
#pragma unroll
    for (int o = 0; o < 4; ++o) { macc[o] = 0ull; s0a[o] = 0.f; s3a[o] = 0.f; }

    stage(0, 0);
    stage(CHUNK, 1);

#pragma unroll 1
    for (int k = 0; k < NCH; ++k) {
        mbar_wait(k & 1 ? mb1 : mb0, (k >> 1) & 1);

        const float* sbuf = s_f2 + (k & 1) * F2BUF + (dy + ty) * SROW + x0l;
        const float* abuf = s_f1 + (k & 1) * F1BUF + ty * XW + x0l;
#pragma unroll
        for (int i = 0; i < CHUNK / 2; ++i) {
            const int c = (i << 1) + ch;
            const float* s = sbuf + c * (SROWS * SROW);
            f2u w[6];
#pragma unroll
            for (int j = 0; j < 6; ++j) w[j].f = *(const float2*)(s + 2 * j);
            f2u a01, a23, am;
            a01.f = *(const float2*)(abuf + c * (TY * XW));
            a23.f = *(const float2*)(abuf + c * (TY * XW) + 2);
            am.u  = pk(a01.f.y, a23.f.x);            // (a1, a2)
            // even dx = 2e
#pragma unroll
            for (int e = 0; e < 5; ++e) {
                fma2(eacc[e][0], a01.u, w[e].u);     // (a0*v[2e],   a1*v[2e+1])
                fma2(eacc[e][1], a23.u, w[e + 1].u); // (a2*v[2e+2], a3*v[2e+3])
            }
            // odd dx = 2o+1
#pragma unroll
            for (int o = 0; o < 4; ++o) {
                fma2(macc[o], am.u, w[o + 1].u);     // (a1*v[2o+2], a2*v[2o+3])
                s0a[o] = fmaf(a01.f.x, w[o].f.y, s0a[o]);       // a0*v[2o+1]
                s3a[o] = fmaf(a23.f.y, w[o + 2].f.x, s3a[o]);   // a3*v[2o+4]
            }
        }
        if (k + 2 < NCH) {
            __syncthreads();
            stage((k + 2) * CHUNK, k & 1);
        }
    }

    // ---- assemble per-dx results
    float a[PATCH][4];
#pragma unroll
    for (int e = 0; e < 5; ++e) {
        unpk(eacc[e][0], a[2 * e][0], a[2 * e][1]);
        unpk(eacc[e][1], a[2 * e][2], a[2 * e][3]);
    }
#pragma unroll
    for (int o = 0; o < 4; ++o) {
        a[2 * o + 1][0] = s0a[o];
        unpk(macc[o], a[2 * o + 1][1], a[2 * o + 1][2]);
        a[2 * o + 1][3] = s3a[o];
    }

    // ---- combine channel halves in-warp (partner lane = xor 16)
#pragma unroll
    for (int d = 0; d < PATCH; ++d)
#pragma unroll
        for (int j = 0; j < 4; ++j)
            a[d][j] += __shfl_xor_sync(0xffffffffu, a[d][j], 16);

    if (ch == 0) {
        float4 iv1 = *(const float4*)(&g_inv1[b][y * Ww + xg]);
        float e[12];
        *(float4*)&e[0] = *(const float4*)(&g_inv2p[b][y + dy][xg]);
        *(float4*)&e[4] = *(const float4*)(&g_inv2p[b][y + dy][xg + 4]);
        *(float4*)&e[8] = *(const float4*)(&g_inv2p[b][y + dy][xg + 8]);

        float* op = out + (size_t)(b * 81 + dy * PATCH) * HW + y * Ww + xg;
#pragma unroll
        for (int d = 0; d < PATCH; ++d) {
            float4 o;
            o.x = fmaxf(a[d][0] * iv1.x * e[d + 0], 0.f);
            o.y = fmaxf(a[d][1] * iv1.y * e[d + 1], 0.f);
            o.z = fmaxf(a[d][2] * iv1.z * e[d + 2], 0.f);
            o.w = fmaxf(a[d][3] * iv1.w * e[d + 3], 0.f);
            *(float4*)(op + d * HW) = o;
        }
    }
}

// ---------------------------------------------------------------------------
extern "C" void kernel_launch(void* const* d_in, const int* in_sizes, int n_in,
                              void* d_out, int out_size) {
    const float* f1 = (const float*)d_in[0];
    const float* f2 = (const float*)d_in[1];
    float* out = (float*)d_out;

    cudaFuncSetAttribute(corr_kernel,
                         cudaFuncAttributeMaxDynamicSharedMemorySize, SMEM_BYTES);

    invnorm_kernel<<<128, 256>>>(f1, f2);
    corr_kernel<<<Bz * (Hh / TY) * 2, NTHR, SMEM_BYTES>>>(f1, f2, out);
}